// round 5
// baseline (speedup 1.0000x reference)
#include <cuda_runtime.h>
#include <cstdint>
#include <cstddef>

#define RR 8
#define NN 300000
#define DD 128
#define AA 64
#define TILE_M 64
#define HSTR 132               // h tile row stride: frag banks 4g+tg distinct
#define WSTR 72                // w chunk row stride: frag banks 8tg+g distinct
#define H_BUF (TILE_M * HSTR)  // 8448 floats
#define W_BUF (32 * WSTR)      // 2304 floats
#define NCHUNK 32              // 8 relations x 4 k-chunks
#define LOG2E 1.4426950408889634f

__device__ __forceinline__ float fast_sigmoid(float x) {
    float e;
    asm("ex2.approx.f32 %0, %1;" : "=f"(e) : "f"(-LOG2E * x));
    float r;
    asm("rcp.approx.f32 %0, %1;" : "=f"(r) : "f"(1.0f + e));
    return r;
}

__device__ __forceinline__ float fast_exp(float x) {
    float e;
    asm("ex2.approx.f32 %0, %1;" : "=f"(e) : "f"(LOG2E * x));
    return e;
}

__device__ __forceinline__ void mma_tf32_16n8k8(float c[4],
                                                const unsigned a[4],
                                                unsigned b0, unsigned b1) {
    asm volatile(
        "mma.sync.aligned.m16n8k8.row.col.f32.tf32.tf32.f32 "
        "{%0,%1,%2,%3}, {%4,%5,%6,%7}, {%8,%9}, {%0,%1,%2,%3};"
        : "+f"(c[0]), "+f"(c[1]), "+f"(c[2]), "+f"(c[3])
        : "r"(a[0]), "r"(a[1]), "r"(a[2]), "r"(a[3]), "r"(b0), "r"(b1));
}

__device__ __forceinline__ void cp_async16(float* dst, const float* src, bool pred) {
    unsigned d = (unsigned)__cvta_generic_to_shared(dst);
    int sz = pred ? 16 : 0;
    asm volatile("cp.async.cg.shared.global [%0], [%1], 16, %2;"
                 :: "r"(d), "l"(src), "r"(sz));
}
#define CP_COMMIT() asm volatile("cp.async.commit_group;")
#define CP_WAIT(n)  asm volatile("cp.async.wait_group %0;" :: "n"(n))

__global__ void __launch_bounds__(256, 2)
fused_online_kernel(const float* __restrict__ h,
                    const float* __restrict__ w1,
                    const float* __restrict__ w2,
                    float* __restrict__ out) {
    extern __shared__ float smem[];
    float* sh_h  = smem;                    // 2 * H_BUF
    float* sh_w  = sh_h + 2 * H_BUF;        // 3 * W_BUF (ring of 3)
    float* sh_w2 = sh_w + 3 * W_BUF;        // RR * AA = 512
    float* sh_prt = sh_w2 + RR * AA;        // 4 planes x 64 rows

    const int tid = threadIdx.x;
    const long node0 = (long)blockIdx.x * TILE_M;

    // stage all w2 once (512 floats)
    sh_w2[tid] = w2[tid];
    sh_w2[tid + 256] = w2[tid + 256];

    // stage full h tile (64 rows x 128 cols = 2048 float4) for relation rr
    auto stage_h = [&](int rr) {
        const float* hg = h + (size_t)rr * NN * DD;
        float* hb = sh_h + (rr & 1) * H_BUF;
        #pragma unroll
        for (int i = 0; i < 8; i++) {
            int idx = tid + i * 256;         // 0..2047
            int row = idx >> 5, c4 = idx & 31;
            long node = node0 + row;
            bool p = node < NN;
            cp_async16(hb + row * HSTR + c4 * 4,
                       hg + (size_t)(p ? node : 0) * DD + c4 * 4, p);
        }
    };
    // stage w1 chunk c (relation c>>2, k-chunk c&3): 32 rows x 64 cols = 512 float4
    auto stage_w = [&](int c) {
        int rr = c >> 2, kc = c & 3;
        const float* wg = w1 + (size_t)rr * DD * AA + kc * 32 * AA;
        float* wb = sh_w + (c % 3) * W_BUF;
        #pragma unroll
        for (int i = 0; i < 2; i++) {
            int idx = tid + i * 256;         // 0..511
            int row = idx >> 4, c4 = idx & 15;
            cp_async16(wb + row * WSTR + c4 * 4, wg + row * AA + c4 * 4, true);
        }
    };

    // prologue: group0 = {H(0), W(0)}, group1 = {W(1)}
    stage_h(0); stage_w(0); CP_COMMIT();
    stage_w(1); CP_COMMIT();
    CP_WAIT(1);   // group0 done

    const int w = tid >> 5, lane = tid & 31;
    const int g = lane >> 2, tg = lane & 3;
    const int m0 = (w & 1) * 32;       // 2-way m split (32 rows)
    const int n0 = (w >> 1) * 16;      // 4-way n split (16 cols)
    const int ng = w >> 1;

    // per-thread output accumulator: row = w*8 + (lane&7), kgroup = lane>>3
    const int orow = (w << 3) | (lane & 7);
    const int okg = lane >> 3;
    float4 o4[8];
    #pragma unroll
    for (int j = 0; j < 8; j++) o4[j] = make_float4(0.f, 0.f, 0.f, 0.f);
    float mrun = -1e30f, srun = 0.f;

    float acc[2][2][4];

    for (int c = 0; c < NCHUNK; c++) {
        const int rr = c >> 2, kc = c & 3;
        __syncthreads();   // sync_a: publishes group c-2; frees buffers for staging

        // stage ahead (one commit group per iteration)
        if (c + 2 < NCHUNK) {
            if (kc == 0 && rr + 1 < RR) stage_h(rr + 1);
            stage_w(c + 2);
            CP_COMMIT();
        }

        if (kc == 0) {
            #pragma unroll
            for (int mt = 0; mt < 2; mt++)
                #pragma unroll
                for (int nt = 0; nt < 2; nt++)
                    #pragma unroll
                    for (int q = 0; q < 4; q++) acc[mt][nt][q] = 0.f;
        }

        const float* hb = sh_h + (rr & 1) * H_BUF;
        const unsigned* hw = (const unsigned*)hb;
        const unsigned* ww = (const unsigned*)(sh_w + (c % 3) * W_BUF);
        const int colbase = kc * 32;

        #pragma unroll
        for (int kt = 0; kt < 4; kt++) {
            unsigned a[2][4];
            #pragma unroll
            for (int mt = 0; mt < 2; mt++) {
                int row = m0 + mt * 16 + g;
                int col = colbase + kt * 8 + tg;
                a[mt][0] = hw[row * HSTR + col];
                a[mt][1] = hw[(row + 8) * HSTR + col];
                a[mt][2] = hw[row * HSTR + col + 4];
                a[mt][3] = hw[(row + 8) * HSTR + col + 4];
            }
            #pragma unroll
            for (int nt = 0; nt < 2; nt++) {
                int nb = n0 + nt * 8;
                unsigned b0 = ww[(kt * 8 + tg) * WSTR + nb + g];
                unsigned b1 = ww[(kt * 8 + tg + 4) * WSTR + nb + g];
                mma_tf32_16n8k8(acc[0][nt], a[0], b0, b1);
                mma_tf32_16n8k8(acc[1][nt], a[1], b0, b1);
            }
        }

        if (kc == 3) {
            // score epilogue: sigmoid, dot w2, reduce over this warp's 16 cols
            float p[4] = {0.f, 0.f, 0.f, 0.f};
            #pragma unroll
            for (int mt = 0; mt < 2; mt++)
                #pragma unroll
                for (int nt = 0; nt < 2; nt++)
                    #pragma unroll
                    for (int q = 0; q < 4; q++) {
                        int col = n0 + nt * 8 + 2 * tg + (q & 1);
                        p[mt * 2 + (q >> 1)] +=
                            fast_sigmoid(acc[mt][nt][q]) * sh_w2[rr * AA + col];
                    }
            #pragma unroll
            for (int o = 1; o < 4; o <<= 1) {
                p[0] += __shfl_xor_sync(0xffffffffu, p[0], o);
                p[1] += __shfl_xor_sync(0xffffffffu, p[1], o);
                p[2] += __shfl_xor_sync(0xffffffffu, p[2], o);
                p[3] += __shfl_xor_sync(0xffffffffu, p[3], o);
            }
            if (tg == 0) {
                #pragma unroll
                for (int mt = 0; mt < 2; mt++) {
                    sh_prt[ng * 64 + m0 + mt * 16 + g]     = p[mt * 2];
                    sh_prt[ng * 64 + m0 + mt * 16 + g + 8] = p[mt * 2 + 1];
                }
            }
            __syncthreads();   // sync_b: prt planes complete

            // online softmax update; h tile still in smem
            float s = sh_prt[orow] + sh_prt[64 + orow] +
                      sh_prt[128 + orow] + sh_prt[192 + orow];
            float mn = fmaxf(mrun, s);
            float f = fast_exp(mrun - mn);
            float e = fast_exp(s - mn);
            srun = srun * f + e;
            mrun = mn;
            const float4* hr = (const float4*)(hb + orow * HSTR);
            #pragma unroll
            for (int j = 0; j < 8; j++) {
                float4 v = hr[okg * 8 + j];
                o4[j].x = o4[j].x * f + e * v.x;
                o4[j].y = o4[j].y * f + e * v.y;
                o4[j].z = o4[j].z * f + e * v.z;
                o4[j].w = o4[j].w * f + e * v.w;
            }
        }

        // end-of-iter wait: group containing W(c+1) must be done before mma(c+1)
        if (c < NCHUNK - 2)       CP_WAIT(1);
        else if (c == NCHUNK - 2) CP_WAIT(0);
    }

    // final normalize + store
    float inv = 1.f / srun;
    long node = node0 + orow;
    if (node < NN) {
        float4* op = (float4*)(out + (size_t)node * DD);
        #pragma unroll
        for (int j = 0; j < 8; j++) {
            float4 t = o4[j];
            t.x *= inv; t.y *= inv; t.z *= inv; t.w *= inv;
            op[okg * 8 + j] = t;
        }
    }
}

extern "C" void kernel_launch(void* const* d_in, const int* in_sizes, int n_in,
                              void* d_out, int out_size) {
    const float* h  = (const float*)d_in[0];
    const float* w1 = (const float*)d_in[1];
    const float* w2 = (const float*)d_in[2];
    float* out = (float*)d_out;

    const int smem_bytes =
        (2 * H_BUF + 3 * W_BUF + RR * AA + 4 * TILE_M) * 4;
    cudaFuncSetAttribute(fused_online_kernel,
                         cudaFuncAttributeMaxDynamicSharedMemorySize, smem_bytes);

    dim3 grid((NN + TILE_M - 1) / TILE_M);
    fused_online_kernel<<<grid, 256, smem_bytes>>>(h, w1, w2, out);
}